// round 1
// baseline (speedup 1.0000x reference)
#include <cuda_runtime.h>
#include <cuda_bf16.h>
#include <math.h>

// Problem constants
#define BB 2
#define TT 1024
#define CC 2048
#define HH 32
#define NN 64
#define BT (BB*TT)              // 2048
#define BTC (BB*TT*CC)          // 4194304

// ---------------------------------------------------------------------------
// Scratch (static device memory; no allocations anywhere)
// ---------------------------------------------------------------------------
// 18 BTC-sized fp32 buffers + LoRA intermediates
#define N_BIG 18
#define U_W_OFF   ((size_t)N_BIG*BTC)
#define U_A_OFF   (U_W_OFF + (size_t)BT*64)
#define U_V_OFF   (U_A_OFF + (size_t)BT*64)
#define U_G_OFF   (U_V_OFF + (size_t)BT*32)
#define SCRATCH_FLOATS (U_G_OFF + (size_t)BT*128)

__device__ float g_scratch[SCRATCH_FLOATS];

// big-buffer slot indices
enum {
    S_XR=0, S_XW, S_XK, S_XV, S_XA, S_XG,
    S_R, S_K, S_V,
    S_DECAY, S_ASIG, S_G,
    S_AW, S_BW, S_KF, S_VF,
    S_O, S_XO
};

// ---------------------------------------------------------------------------
// K1: token shift + 6-way mix
// ---------------------------------------------------------------------------
__global__ __launch_bounds__(256) void mix_kernel(
    const float* __restrict__ h, const float* __restrict__ shift,
    const float* __restrict__ mr, const float* __restrict__ mw,
    const float* __restrict__ mk, const float* __restrict__ mv,
    const float* __restrict__ ma, const float* __restrict__ mg,
    float* __restrict__ oxr, float* __restrict__ oxw,
    float* __restrict__ oxk, float* __restrict__ oxv,
    float* __restrict__ oxa, float* __restrict__ oxg)
{
    int gid = blockIdx.x * 256 + threadIdx.x;      // 0..1048575
    int row = gid >> 9;                            // 0..2047 (bt)
    int c   = (gid & 511) << 2;
    int t   = row & (TT-1);
    int b   = row >> 10;
    size_t off = (size_t)row * CC + c;

    float4 hv = *(const float4*)&h[off];
    float4 pv;
    if (t == 0) pv = *(const float4*)&shift[(size_t)b*CC + c];
    else        pv = *(const float4*)&h[off - CC];
    float4 xx = make_float4(pv.x-hv.x, pv.y-hv.y, pv.z-hv.z, pv.w-hv.w);

#define DO_MIX(dst, mvec)                                            \
    {   float4 m = *(const float4*)&mvec[c];                         \
        float4 o = make_float4(hv.x + xx.x*m.x, hv.y + xx.y*m.y,     \
                               hv.z + xx.z*m.z, hv.w + xx.w*m.w);    \
        *(float4*)&dst[off] = o; }
    DO_MIX(oxr, mr) DO_MIX(oxw, mw) DO_MIX(oxk, mk)
    DO_MIX(oxv, mv) DO_MIX(oxa, ma) DO_MIX(oxg, mg)
#undef DO_MIX
}

// ---------------------------------------------------------------------------
// K2: big fp32 GEMM  Y[2048,2048] = A[2048,2048] @ Bw[2048,2048]^T
//     128x128 block tile, 8x8 thread tile, BK=16, register prefetch
// ---------------------------------------------------------------------------
__global__ __launch_bounds__(256) void gemm_nt_2048(
    const float* __restrict__ A, const float* __restrict__ Bw,
    float* __restrict__ Y)
{
    __shared__ float As[16][132];
    __shared__ float Bs[16][132];
    const int tid = threadIdx.x;
    const int bm = blockIdx.y << 7;
    const int bn = blockIdx.x << 7;

    float4 pa[2], pb[2];

#define GLOAD(k0)                                                         \
    {   _Pragma("unroll")                                                 \
        for (int i = 0; i < 2; i++) {                                     \
            int lin = tid + (i << 8);                                     \
            int row = lin >> 2, cc = (lin & 3) << 2;                      \
            pa[i] = *(const float4*)&A [(size_t)(bm+row)*CC + (k0) + cc]; \
            pb[i] = *(const float4*)&Bw[(size_t)(bn+row)*CC + (k0) + cc]; \
        } }
#define SSTORE()                                                          \
    {   _Pragma("unroll")                                                 \
        for (int i = 0; i < 2; i++) {                                     \
            int lin = tid + (i << 8);                                     \
            int row = lin >> 2, cc = (lin & 3) << 2;                      \
            As[cc+0][row]=pa[i].x; As[cc+1][row]=pa[i].y;                 \
            As[cc+2][row]=pa[i].z; As[cc+3][row]=pa[i].w;                 \
            Bs[cc+0][row]=pb[i].x; Bs[cc+1][row]=pb[i].y;                 \
            Bs[cc+2][row]=pb[i].z; Bs[cc+3][row]=pb[i].w;                 \
        } }

    float acc[8][8];
#pragma unroll
    for (int i=0;i<8;i++)
#pragma unroll
        for (int j=0;j<8;j++) acc[i][j]=0.f;

    const int m0 = (tid >> 4) << 3;
    const int n0 = (tid & 15) << 3;

    GLOAD(0); SSTORE(); __syncthreads();

    for (int k0 = 16; k0 <= 2048; k0 += 16) {
        if (k0 < 2048) GLOAD(k0);
#pragma unroll
        for (int kk = 0; kk < 16; kk++) {
            float4 a0 = *(const float4*)&As[kk][m0];
            float4 a1 = *(const float4*)&As[kk][m0+4];
            float4 b0 = *(const float4*)&Bs[kk][n0];
            float4 b1 = *(const float4*)&Bs[kk][n0+4];
            float am[8] = {a0.x,a0.y,a0.z,a0.w,a1.x,a1.y,a1.z,a1.w};
            float bv[8] = {b0.x,b0.y,b0.z,b0.w,b1.x,b1.y,b1.z,b1.w};
#pragma unroll
            for (int i=0;i<8;i++)
#pragma unroll
                for (int j=0;j<8;j++)
                    acc[i][j] += am[i]*bv[j];
        }
        __syncthreads();
        if (k0 < 2048) { SSTORE(); __syncthreads(); }
    }
#undef GLOAD
#undef SSTORE

#pragma unroll
    for (int i=0;i<8;i++) {
        float4 v0 = make_float4(acc[i][0],acc[i][1],acc[i][2],acc[i][3]);
        float4 v1 = make_float4(acc[i][4],acc[i][5],acc[i][6],acc[i][7]);
        size_t o = (size_t)(bm+m0+i)*CC + bn + n0;
        *(float4*)&Y[o]   = v0;
        *(float4*)&Y[o+4] = v1;
    }
}

// ---------------------------------------------------------------------------
// K3: LoRA stage 1: U[BT,D] = act( X[BT,2048] @ G[2048,D] )
//     ACT: 0=none, 1=tanh, 2=sigmoid
// ---------------------------------------------------------------------------
template<int D, int ACT>
__global__ __launch_bounds__(256) void lora1_kernel(
    const float* __restrict__ X, const float* __restrict__ G,
    float* __restrict__ U)
{
    constexpr int BM = 16, BK = 32;
    constexpr int STEP = 256 / D;
    constexpr int NR = BM / STEP;            // D/16
    constexpr int NG = (BK*D) / (4*256);     // float4 G loads per thread
    __shared__ float Xs[BK][BM+1];
    __shared__ float Gs[BK][D];

    const int tid = threadIdx.x;
    const int bm = blockIdx.x * BM;
    const int c = tid % D;
    const int rg = tid / D;

    float acc[NR];
#pragma unroll
    for (int i=0;i<NR;i++) acc[i]=0.f;

    for (int k0 = 0; k0 < 2048; k0 += BK) {
        if (tid < 128) {
            int row = tid >> 3, cc = (tid & 7) << 2;
            float4 xv = *(const float4*)&X[(size_t)(bm+row)*CC + k0 + cc];
            Xs[cc+0][row]=xv.x; Xs[cc+1][row]=xv.y;
            Xs[cc+2][row]=xv.z; Xs[cc+3][row]=xv.w;
        }
#pragma unroll
        for (int i=0;i<NG;i++){
            int lin = tid + (i<<8);
            int kr = lin / (D/4);
            int cc = (lin % (D/4)) << 2;
            *(float4*)&Gs[kr][cc] = *(const float4*)&G[(size_t)(k0+kr)*D + cc];
        }
        __syncthreads();
#pragma unroll
        for (int kk=0;kk<BK;kk++){
            float gv = Gs[kk][c];
#pragma unroll
            for (int i=0;i<NR;i++)
                acc[i] += Xs[kk][rg + i*STEP] * gv;
        }
        __syncthreads();
    }
#pragma unroll
    for (int i=0;i<NR;i++){
        float y = acc[i];
        if (ACT==1) y = tanhf(y);
        else if (ACT==2) y = 1.f/(1.f+expf(-y));
        U[(size_t)(bm + rg + i*STEP)*D + c] = y;
    }
}

// ---------------------------------------------------------------------------
// K4: LoRA stage 2 + epilogue.
//   MODE 0: decay = e^{-1/2} * sigmoid(acc + w0)
//   MODE 1: sigmoid(acc + a0)
//   MODE 2: v lerp:  out = vraw + (v_first - vraw)*sigmoid(acc + v0)
//   MODE 3: plain (g path)
// ---------------------------------------------------------------------------
template<int D, int MODE>
__global__ __launch_bounds__(256) void stage2_kernel(
    const float* __restrict__ U, const float* __restrict__ V2,
    const float* __restrict__ bias, float* __restrict__ out,
    const float* __restrict__ e1, const float* __restrict__ e2)
{
    constexpr int ROWS = 32;
    constexpr int NL = (ROWS*D)/(4*256);
    __shared__ float Us[ROWS][D];
    const int tid = threadIdx.x;
    const int row0 = blockIdx.y * ROWS;
    const int c = blockIdx.x * 256 + tid;

#pragma unroll
    for (int i=0;i<NL;i++){
        int lin = tid + (i<<8);
        int rr = lin / (D/4), cc = (lin % (D/4)) << 2;
        *(float4*)&Us[rr][cc] = *(const float4*)&U[(size_t)(row0+rr)*D + cc];
    }
    __syncthreads();

    float acc[ROWS];
#pragma unroll
    for (int r=0;r<ROWS;r++) acc[r]=0.f;

#pragma unroll
    for (int d0=0; d0<D; d0+=4){
        float v0 = V2[(size_t)(d0+0)*CC + c];
        float v1 = V2[(size_t)(d0+1)*CC + c];
        float v2 = V2[(size_t)(d0+2)*CC + c];
        float v3 = V2[(size_t)(d0+3)*CC + c];
#pragma unroll
        for (int r=0;r<ROWS;r++){
            float4 u = *(const float4*)&Us[r][d0];
            acc[r] += u.x*v0 + u.y*v1 + u.z*v2 + u.w*v3;
        }
    }
    float bv = (MODE==3) ? 0.f : bias[c];
#pragma unroll
    for (int r=0;r<ROWS;r++){
        size_t idx = (size_t)(row0+r)*CC + c;
        float y = acc[r] + bv;
        if (MODE==0)      out[idx] = 0.6065306597126334f * (1.f/(1.f+expf(-y)));
        else if (MODE==1) out[idx] = 1.f/(1.f+expf(-y));
        else if (MODE==2) {
            float s = 1.f/(1.f+expf(-y));
            float vr = e1[idx];
            out[idx] = vr + (e2[idx]-vr)*s;
        } else            out[idx] = y;
    }
}

// ---------------------------------------------------------------------------
// K5: per-(b,t,h) prep: normalized kk -> aw=-kk, bw=kk*a, k_final
//     4 heads per 256-thread block
// ---------------------------------------------------------------------------
__global__ __launch_bounds__(256) void prep_kernel(
    const float* __restrict__ k, const float* __restrict__ asig,
    const float* __restrict__ kkvec, const float* __restrict__ kavec,
    float* __restrict__ aw, float* __restrict__ bw, float* __restrict__ kf)
{
    const int tid = threadIdx.x;
    const int g = tid >> 6, n = tid & 63;
    const size_t head = (size_t)blockIdx.x*4 + g;
    const size_t idx = head*64 + n;
    const int c = (int)(idx & (CC-1));

    float kv = k[idx];
    float kk = kv * kkvec[c];
    float ss = kk*kk;
#pragma unroll
    for (int off=16; off; off>>=1) ss += __shfl_xor_sync(0xffffffffu, ss, off);
    __shared__ float red[8];
    if ((tid & 31)==0) red[tid>>5] = ss;
    __syncthreads();
    float tot = red[g*2] + red[g*2+1];
    float inv = 1.f / fmaxf(sqrtf(tot), 1e-12f);
    float kkn = kk * inv;
    float a = asig[idx];
    aw[idx] = -kkn;
    bw[idx] = kkn * a;
    kf[idx] = kv + kavec[c]*(kv*a - kv);
}

// ---------------------------------------------------------------------------
// K6: WKV7 recurrence. One block per (b,h). 128 threads: thread = (v, k-half),
//     S[32] in registers, 2-deep global->smem prefetch.
// ---------------------------------------------------------------------------
__global__ __launch_bounds__(128) void wkv_kernel(
    const float* __restrict__ r, const float* __restrict__ k,
    const float* __restrict__ v, const float* __restrict__ d,
    const float* __restrict__ aw, const float* __restrict__ bw,
    const float* __restrict__ s0, float* __restrict__ o)
{
    const int bh = blockIdx.x;            // 0..63
    const int b = bh >> 5, hh = bh & 31;
    const int tid = threadIdx.x;
    const int vr = tid >> 1;
    const int koff = (tid & 1) * 32;
    const int n = tid & 63;

    float S[32];
    {
        const float* sp = s0 + ((size_t)bh*64 + vr)*64 + koff;
#pragma unroll
        for (int i=0;i<32;i++) S[i] = sp[i];
    }

    __shared__ float sh[2][6][64];        // 0=r 1=k 2=v 3=d 4=aw 5=bw
    const size_t rowbase = (size_t)b*TT*CC + hh*64;

    float p0, p1, p2;
    // t = 0 direct into smem
    {
        size_t idx = rowbase + n;
        if (tid < 64) { sh[0][0][n]=r[idx]; sh[0][1][n]=k[idx]; sh[0][2][n]=v[idx]; }
        else          { sh[0][3][n]=d[idx]; sh[0][4][n]=aw[idx]; sh[0][5][n]=bw[idx]; }
    }
    // t = 1 into regs
    {
        size_t idx = rowbase + (size_t)1*CC + n;
        if (tid < 64) { p0=r[idx]; p1=k[idx]; p2=v[idx]; }
        else          { p0=d[idx]; p1=aw[idx]; p2=bw[idx]; }
    }
    __syncthreads();

    for (int t = 0; t < TT; t++) {
        const int buf = t & 1;
        if (t+1 < TT) {
            if (tid < 64) { sh[buf^1][0][n]=p0; sh[buf^1][1][n]=p1; sh[buf^1][2][n]=p2; }
            else          { sh[buf^1][3][n]=p0; sh[buf^1][4][n]=p1; sh[buf^1][5][n]=p2; }
        }
        if (t+2 < TT) {
            size_t idx = rowbase + (size_t)(t+2)*CC + n;
            if (tid < 64) { p0=r[idx]; p1=k[idx]; p2=v[idx]; }
            else          { p0=d[idx]; p1=aw[idx]; p2=bw[idx]; }
        }

        const float* shr = sh[buf][0];
        const float* shk = sh[buf][1];
        const float* shv = sh[buf][2];
        const float* shd = sh[buf][3];
        const float* sha = sh[buf][4];
        const float* shb = sh[buf][5];

        float sa0=0.f, sa1=0.f, sa2=0.f, sa3=0.f;
#pragma unroll
        for (int i=0;i<32;i+=4){
            float4 a4 = *(const float4*)&sha[koff+i];
            sa0 += S[i+0]*a4.x; sa1 += S[i+1]*a4.y;
            sa2 += S[i+2]*a4.z; sa3 += S[i+3]*a4.w;
        }
        float sa = (sa0+sa1)+(sa2+sa3);
        sa += __shfl_xor_sync(0xffffffffu, sa, 1);

        const float vt = shv[vr];
        float o0=0.f,o1=0.f,o2=0.f,o3=0.f;
#pragma unroll
        for (int i=0;i<32;i+=4){
            float4 d4 = *(const float4*)&shd[koff+i];
            float4 b4 = *(const float4*)&shb[koff+i];
            float4 k4 = *(const float4*)&shk[koff+i];
            float4 r4 = *(const float4*)&shr[koff+i];
            S[i+0] = S[i+0]*d4.x + sa*b4.x + vt*k4.x;
            S[i+1] = S[i+1]*d4.y + sa*b4.y + vt*k4.y;
            S[i+2] = S[i+2]*d4.z + sa*b4.z + vt*k4.z;
            S[i+3] = S[i+3]*d4.w + sa*b4.w + vt*k4.w;
            o0 += S[i+0]*r4.x; o1 += S[i+1]*r4.y;
            o2 += S[i+2]*r4.z; o3 += S[i+3]*r4.w;
        }
        float oo = (o0+o1)+(o2+o3);
        oo += __shfl_xor_sync(0xffffffffu, oo, 1);
        if ((tid & 1)==0) o[rowbase + (size_t)t*CC + vr] = oo;
        __syncthreads();
    }
}

// ---------------------------------------------------------------------------
// K7: group norm + per-head bonus + gate multiply
// ---------------------------------------------------------------------------
__global__ __launch_bounds__(256) void gn_kernel(
    const float* __restrict__ o, const float* __restrict__ r,
    const float* __restrict__ kf, const float* __restrict__ vf,
    const float* __restrict__ gg, const float* __restrict__ rk,
    const float* __restrict__ gnw, const float* __restrict__ gnb,
    float* __restrict__ xo)
{
    const int tid = threadIdx.x;
    const int g = tid >> 6, n = tid & 63;
    const size_t head = (size_t)blockIdx.x*4 + g;
    const int h = (int)(head & (HH-1));
    const size_t idx = head*64 + n;
    const int c = h*64 + n;

    float ov = o[idx];
    float rv = r[idx], kv = kf[idx];
    float s1 = ov, s2 = ov*ov, s3 = rv*kv*rk[c];
#pragma unroll
    for (int off=16; off; off>>=1){
        s1 += __shfl_xor_sync(0xffffffffu, s1, off);
        s2 += __shfl_xor_sync(0xffffffffu, s2, off);
        s3 += __shfl_xor_sync(0xffffffffu, s3, off);
    }
    __shared__ float red[8][3];
    if ((tid & 31)==0){ int w = tid>>5; red[w][0]=s1; red[w][1]=s2; red[w][2]=s3; }
    __syncthreads();
    float S1 = red[g*2][0]+red[g*2+1][0];
    float S2 = red[g*2][1]+red[g*2+1][1];
    float S3 = red[g*2][2]+red[g*2+1][2];
    float mu = S1*(1.f/64.f);
    float var = S2*(1.f/64.f) - mu*mu;
    float y = (ov-mu)*rsqrtf(var + 6.4e-4f)*gnw[c] + gnb[c] + S3*vf[idx];
    xo[idx] = y * gg[idx];
}

// ---------------------------------------------------------------------------
// Launch
// ---------------------------------------------------------------------------
extern "C" void kernel_launch(void* const* d_in, const int* in_sizes, int n_in,
                              void* d_out, int out_size)
{
    const float* h      = (const float*)d_in[0];
    const float* shift  = (const float*)d_in[1];
    const float* s0     = (const float*)d_in[2];
    const float* vfirst = (const float*)d_in[3];
    const float* x_r = (const float*)d_in[4];
    const float* x_w = (const float*)d_in[5];
    const float* x_k = (const float*)d_in[6];
    const float* x_v = (const float*)d_in[7];
    const float* x_a = (const float*)d_in[8];
    const float* x_g = (const float*)d_in[9];
    const float* w0 = (const float*)d_in[10];
    const float* w1 = (const float*)d_in[11];
    const float* w2 = (const float*)d_in[12];
    const float* a0 = (const float*)d_in[13];
    const float* a1 = (const float*)d_in[14];
    const float* a2 = (const float*)d_in[15];
    const float* v0 = (const float*)d_in[16];
    const float* v1 = (const float*)d_in[17];
    const float* v2 = (const float*)d_in[18];
    const float* g1 = (const float*)d_in[19];
    const float* g2 = (const float*)d_in[20];
    const float* k_k = (const float*)d_in[21];
    const float* k_a = (const float*)d_in[22];
    const float* r_k = (const float*)d_in[23];
    const float* W_r = (const float*)d_in[24];
    const float* W_k = (const float*)d_in[25];
    const float* W_v = (const float*)d_in[26];
    const float* W_o = (const float*)d_in[27];
    const float* gnw = (const float*)d_in[28];
    const float* gnb = (const float*)d_in[29];
    float* out = (float*)d_out;

    float* S = nullptr;
    cudaGetSymbolAddress((void**)&S, g_scratch);

    float* xr = S + (size_t)S_XR*BTC;   float* xw = S + (size_t)S_XW*BTC;
    float* xk = S + (size_t)S_XK*BTC;   float* xv = S + (size_t)S_XV*BTC;
    float* xa = S + (size_t)S_XA*BTC;   float* xg = S + (size_t)S_XG*BTC;
    float* rb = S + (size_t)S_R*BTC;    float* kb = S + (size_t)S_K*BTC;
    float* vb = S + (size_t)S_V*BTC;
    float* decay = S + (size_t)S_DECAY*BTC;
    float* asig  = S + (size_t)S_ASIG*BTC;
    float* gbuf  = S + (size_t)S_G*BTC;
    float* awb = S + (size_t)S_AW*BTC;  float* bwb = S + (size_t)S_BW*BTC;
    float* kfb = S + (size_t)S_KF*BTC;  float* vfb = S + (size_t)S_VF*BTC;
    float* ob  = S + (size_t)S_O*BTC;   float* xob = S + (size_t)S_XO*BTC;
    float* Uw = S + U_W_OFF;  float* Ua = S + U_A_OFF;
    float* Uv = S + U_V_OFF;  float* Ug = S + U_G_OFF;

    // 1. token shift + mixes
    mix_kernel<<<4096, 256>>>(h, shift, x_r, x_w, x_k, x_v, x_a, x_g,
                              xr, xw, xk, xv, xa, xg);

    // 2. big projections
    dim3 gg(16,16);
    gemm_nt_2048<<<gg, 256>>>(xr, W_r, rb);
    gemm_nt_2048<<<gg, 256>>>(xk, W_k, kb);
    gemm_nt_2048<<<gg, 256>>>(xv, W_v, vb);

    // 3. LoRA stage 1
    lora1_kernel<64, 1><<<128, 256>>>(xw, w1, Uw);   // tanh
    lora1_kernel<64, 0><<<128, 256>>>(xa, a1, Ua);
    lora1_kernel<32, 0><<<128, 256>>>(xv, v1, Uv);
    lora1_kernel<128,2><<<128, 256>>>(xg, g1, Ug);   // sigmoid

    // 4. LoRA stage 2 + epilogues
    dim3 g2d(8, 64);
    stage2_kernel<64, 0><<<g2d, 256>>>(Uw, w2, w0, decay, nullptr, nullptr);
    stage2_kernel<64, 1><<<g2d, 256>>>(Ua, a2, a0, asig, nullptr, nullptr);
    stage2_kernel<32, 2><<<g2d, 256>>>(Uv, v2, v0, vfb, vb, vfirst);
    stage2_kernel<128,3><<<g2d, 256>>>(Ug, g2, nullptr, gbuf, nullptr, nullptr);

    // 5. kk-normalize / k lerp prep
    prep_kernel<<<BT*HH/4, 256>>>(kb, asig, k_k, k_a, awb, bwb, kfb);

    // 6. WKV7 recurrence
    wkv_kernel<<<BB*HH, 128>>>(rb, kfb, vfb, decay, awb, bwb, s0, ob);

    // 7. group norm + bonus + gate
    gn_kernel<<<BT*HH/4, 256>>>(ob, rb, kfb, vfb, gbuf, r_k, gnw, gnb, xob);

    // 8. output projection
    gemm_nt_2048<<<gg, 256>>>(xob, W_o, out);
}